// round 2
// baseline (speedup 1.0000x reference)
#include <cuda_runtime.h>
#include <math.h>

#define NPTS 1024
#define KNB  16
#define DIM  64
#define NA   12
#define PH   64
#define AH   256
#define STR  20   // shared row stride (floats): 16B-aligned + bank-spread

typedef unsigned long long u64t;

// ---- scratch (device globals; no allocation allowed) ----
__device__ int   g_idx[NPTS * KNB];
__device__ float g_q[NPTS * NA * DIM];
__device__ float g_k[NPTS * NA * DIM];
__device__ float g_v[NPTS * NA * DIM];

// ---- packed fp32x2 helpers (Blackwell FFMA2 pipe) ----
__device__ __forceinline__ u64t pack2(float lo, float hi) {
    u64t r; asm("mov.b64 %0, {%1,%2};" : "=l"(r) : "f"(lo), "f"(hi)); return r;
}
__device__ __forceinline__ u64t dup2(float v) {
    u64t r; asm("mov.b64 %0, {%1,%1};" : "=l"(r) : "f"(v)); return r;
}
__device__ __forceinline__ void fma2(u64t& acc, u64t a, u64t b) {
    asm("fma.rn.f32x2 %0, %1, %2, %0;" : "+l"(acc) : "l"(a), "l"(b));
}
__device__ __forceinline__ float2 unpk2(u64t v) {
    float2 f; asm("mov.b64 {%0,%1}, %2;" : "=f"(f.x), "=f"(f.y) : "l"(v)); return f;
}

// ===================================================================
// Kernel 1: fused KNN + QKV. One 256-thread block per point n.
//   warp 0  : KNN (32 dists/lane in regs, 16 warp-argmin rounds)
//   warps1-7: stage feats[:, n, :] into smem
//   then all: qkv[j,n,a] = sum_i to_qkv[j,i] * feats[i,n,a]
// Output TRANSPOSED to [n][a][c] so attn gathers are contiguous rows.
// ===================================================================
__global__ __launch_bounds__(256) void prep_kernel(
    const float* __restrict__ xyz,       // [3][1024]
    const float* __restrict__ feats,     // [64][1024][12]
    const float* __restrict__ to_qkv)    // [192][64]
{
    __shared__ float sf[DIM * NA];       // feats[:, n, :]
    int n = blockIdx.x;
    int t = threadIdx.x;

    if (t < 32) {
        // ---------------- KNN (warp 0) ----------------
        int lane = t;
        float px = xyz[n], py = xyz[NPTS + n], pz = xyz[2 * NPTS + n];
        float sqn = px * px + py * py + pz * pz;
        float d[32];
#pragma unroll
        for (int j = 0; j < 32; j++) {
            int m = lane + j * 32;
            float qx = xyz[m], qy = xyz[NPTS + m], qz = xyz[2 * NPTS + m];
            float sqm = qx * qx + qy * qy + qz * qz;
            d[j] = sqn + sqm - 2.0f * (px * qx + py * qy + pz * qz);
        }
        for (int tt = 0; tt < KNB; tt++) {
            float best = 3.4e38f;
            int bidx = 1 << 30;
#pragma unroll
            for (int j = 0; j < 32; j++) {
                int m = lane + j * 32;
                if (d[j] < best || (d[j] == best && m < bidx)) { best = d[j]; bidx = m; }
            }
#pragma unroll
            for (int off = 16; off; off >>= 1) {
                float ob = __shfl_xor_sync(0xffffffffu, best, off);
                int   oi = __shfl_xor_sync(0xffffffffu, bidx, off);
                if (ob < best || (ob == best && oi < bidx)) { best = ob; bidx = oi; }
            }
            if (lane == 0) g_idx[n * KNB + tt] = bidx;
            if ((bidx & 31) == lane) {
                int jj = bidx >> 5;
#pragma unroll
                for (int j = 0; j < 32; j++) if (j == jj) d[j] = 3.4e38f;
            }
        }
    } else {
        // ---------------- stage feats (warps 1-7) ----------------
        for (int idx = t - 32; idx < DIM * NA; idx += 224) {
            int i = idx / NA, a = idx % NA;
            sf[idx] = feats[(i * NPTS + n) * NA + a];
        }
    }
    __syncthreads();

    // ---------------- QKV (all 256 threads) ----------------
    for (int o = t; o < 3 * DIM * NA; o += 256) {
        int j = o / NA, a = o % NA;
        const float* w = to_qkv + j * DIM;
        float acc = 0.0f;
#pragma unroll 16
        for (int i = 0; i < DIM; i++) acc += w[i] * sf[i * NA + a];
        int c = j & (DIM - 1);
        float* dst = (j < DIM) ? g_q : (j < 2 * DIM ? g_k : g_v);
        dst[(n * NA + a) * DIM + c] = acc;
    }
}

// ===================================================================
// Kernel 2: fused attention. One 256-thread block per (n, a).
// Hot GEMM phases (C/E/F) use packed fp32x2 FFMA2.
// ===================================================================
__global__ __launch_bounds__(256) void attn_kernel(
    const float* __restrict__ xyz,       // [3][1024]
    const float* __restrict__ anchors,   // [12][3][3]
    const float* __restrict__ P1,        // [64][3]
    const float* __restrict__ P2,        // [64][64]
    const float* __restrict__ W1,        // [256][64]
    const float* __restrict__ W2,        // [64][256]
    float* __restrict__ out)             // [64][1024][12]
{
    __shared__ float s_q[DIM];
    __shared__ float s_gx[3][KNB];
    __shared__ int   s_idx[KNB];
    __shared__ float s_sim[DIM * STR];   // also reused for s2 in phase F
    __shared__ float s_vg[DIM * STR];
    __shared__ float s_h[AH * STR];      // pe1 aliases the front of this
    float* s_pe1 = s_h;

    int a = blockIdx.x % NA;
    int n = blockIdx.x / NA;
    int t = threadIdx.x;

    // ---- Phase A: neighbor idx, rotated rel pos, q load ----
    if (t < KNB) {
        int m = g_idx[n * KNB + t];
        s_idx[t] = m;
        float rx = xyz[n]            - xyz[m];
        float ry = xyz[NPTS + n]     - xyz[NPTS + m];
        float rz = xyz[2 * NPTS + n] - xyz[2 * NPTS + m];
        const float* A = anchors + a * 9;
        s_gx[0][t] = A[0] * rx + A[1] * ry + A[2] * rz;
        s_gx[1][t] = A[3] * rx + A[4] * ry + A[5] * rz;
        s_gx[2][t] = A[6] * rx + A[7] * ry + A[8] * rz;
    }
    if (t >= 64 && t < 64 + DIM) {
        int c = t - 64;
        s_q[c] = g_q[(n * NA + a) * DIM + c];
    }
    __syncthreads();

    // ---- Phase B: pe1[j][k] = relu(P1[j,:] . gx[:,k]) ----
    {
        int j = t >> 2, kq = t & 3, k0 = kq * 4;
        float p0 = P1[j * 3 + 0], p1 = P1[j * 3 + 1], p2 = P1[j * 3 + 2];
        float4 r;
        r.x = fmaxf(p0 * s_gx[0][k0 + 0] + p1 * s_gx[1][k0 + 0] + p2 * s_gx[2][k0 + 0], 0.0f);
        r.y = fmaxf(p0 * s_gx[0][k0 + 1] + p1 * s_gx[1][k0 + 1] + p2 * s_gx[2][k0 + 1], 0.0f);
        r.z = fmaxf(p0 * s_gx[0][k0 + 2] + p1 * s_gx[1][k0 + 2] + p2 * s_gx[2][k0 + 2], 0.0f);
        r.w = fmaxf(p0 * s_gx[0][k0 + 3] + p1 * s_gx[1][k0 + 3] + p2 * s_gx[2][k0 + 3], 0.0f);
        *(float4*)&s_pe1[j * STR + k0] = r;
    }
    __syncthreads();

    // ---- Phase C: pe = P2 @ pe1 ; gather k/v ; build sim and v_g ----
    {
        int c = t >> 2, kq = t & 3, k0 = kq * 4;
        u64t pe0 = 0, pe1acc = 0;        // 4 k-values as 2 f32x2
        const float* P2row = P2 + c * PH;
#pragma unroll
        for (int j4 = 0; j4 < PH / 4; j4++) {
            float4 w = *(const float4*)(P2row + j4 * 4);
            ulonglong2 v0 = *(const ulonglong2*)&s_pe1[(j4 * 4 + 0) * STR + k0];
            ulonglong2 v1 = *(const ulonglong2*)&s_pe1[(j4 * 4 + 1) * STR + k0];
            ulonglong2 v2 = *(const ulonglong2*)&s_pe1[(j4 * 4 + 2) * STR + k0];
            ulonglong2 v3 = *(const ulonglong2*)&s_pe1[(j4 * 4 + 3) * STR + k0];
            u64t wx = dup2(w.x), wy = dup2(w.y), wz = dup2(w.z), ww = dup2(w.w);
            fma2(pe0, wx, v0.x); fma2(pe1acc, wx, v0.y);
            fma2(pe0, wy, v1.x); fma2(pe1acc, wy, v1.y);
            fma2(pe0, wz, v2.x); fma2(pe1acc, wz, v2.y);
            fma2(pe0, ww, v3.x); fma2(pe1acc, ww, v3.y);
        }
        float2 pA = unpk2(pe0), pB = unpk2(pe1acc);
        float qc = s_q[c];
        int m0 = s_idx[k0 + 0], m1 = s_idx[k0 + 1], m2 = s_idx[k0 + 2], m3 = s_idx[k0 + 3];
        int b0 = (m0 * NA + a) * DIM + c;
        int b1 = (m1 * NA + a) * DIM + c;
        int b2 = (m2 * NA + a) * DIM + c;
        int b3 = (m3 * NA + a) * DIM + c;
        float4 sim, vg;
        sim.x = qc - g_k[b0] + pA.x;  vg.x = g_v[b0] + pA.x;
        sim.y = qc - g_k[b1] + pA.y;  vg.y = g_v[b1] + pA.y;
        sim.z = qc - g_k[b2] + pB.x;  vg.z = g_v[b2] + pB.x;
        sim.w = qc - g_k[b3] + pB.y;  vg.w = g_v[b3] + pB.y;
        *(float4*)&s_sim[c * STR + k0] = sim;
        *(float4*)&s_vg[c * STR + k0]  = vg;
    }
    __syncthreads();

    // ---- Phase E: h[r][0..15] = relu(W1[r,:] @ sim), 8 f32x2 accs ----
    {
        int r = t;
        u64t h0 = 0, h1 = 0, h2 = 0, h3 = 0, h4a = 0, h5 = 0, h6 = 0, h7 = 0;
        const float* W1row = W1 + r * DIM;
#pragma unroll 4
        for (int c4 = 0; c4 < DIM / 4; c4++) {
            float4 w = __ldg((const float4*)(W1row + c4 * 4));
            float wsel[4] = {w.x, w.y, w.z, w.w};
#pragma unroll
            for (int cc = 0; cc < 4; cc++) {
                int c = c4 * 4 + cc;
                u64t wd = dup2(wsel[cc]);
                ulonglong2 sA = *(const ulonglong2*)&s_sim[c * STR + 0];
                ulonglong2 sB = *(const ulonglong2*)&s_sim[c * STR + 4];
                ulonglong2 sC = *(const ulonglong2*)&s_sim[c * STR + 8];
                ulonglong2 sD = *(const ulonglong2*)&s_sim[c * STR + 12];
                fma2(h0, wd, sA.x); fma2(h1, wd, sA.y);
                fma2(h2, wd, sB.x); fma2(h3, wd, sB.y);
                fma2(h4a, wd, sC.x); fma2(h5, wd, sC.y);
                fma2(h6, wd, sD.x); fma2(h7, wd, sD.y);
            }
        }
        float2 f0 = unpk2(h0), f1 = unpk2(h1), f2 = unpk2(h2), f3 = unpk2(h3);
        float2 f4 = unpk2(h4a), f5 = unpk2(h5), f6 = unpk2(h6), f7 = unpk2(h7);
        float4 o0 = make_float4(fmaxf(f0.x, 0.f), fmaxf(f0.y, 0.f), fmaxf(f1.x, 0.f), fmaxf(f1.y, 0.f));
        float4 o1 = make_float4(fmaxf(f2.x, 0.f), fmaxf(f2.y, 0.f), fmaxf(f3.x, 0.f), fmaxf(f3.y, 0.f));
        float4 o2 = make_float4(fmaxf(f4.x, 0.f), fmaxf(f4.y, 0.f), fmaxf(f5.x, 0.f), fmaxf(f5.y, 0.f));
        float4 o3 = make_float4(fmaxf(f6.x, 0.f), fmaxf(f6.y, 0.f), fmaxf(f7.x, 0.f), fmaxf(f7.y, 0.f));
        *(float4*)&s_h[r * STR + 0]  = o0;
        *(float4*)&s_h[r * STR + 4]  = o1;
        *(float4*)&s_h[r * STR + 8]  = o2;
        *(float4*)&s_h[r * STR + 12] = o3;
    }
    __syncthreads();

    // ---- Phase F: s2[c][k0..k0+3] = W2[c,:] @ h  (reuse s_sim) ----
    {
        int c = t >> 2, kq = t & 3, k0 = kq * 4;
        u64t a0 = 0, a1 = 0;             // 4 k-values as 2 f32x2
        const float* W2row = W2 + c * AH;
#pragma unroll 8
        for (int h4 = 0; h4 < AH / 4; h4++) {
            float4 w = __ldg((const float4*)(W2row + h4 * 4));
            ulonglong2 r0 = *(const ulonglong2*)&s_h[(h4 * 4 + 0) * STR + k0];
            ulonglong2 r1 = *(const ulonglong2*)&s_h[(h4 * 4 + 1) * STR + k0];
            ulonglong2 r2 = *(const ulonglong2*)&s_h[(h4 * 4 + 2) * STR + k0];
            ulonglong2 r3 = *(const ulonglong2*)&s_h[(h4 * 4 + 3) * STR + k0];
            u64t wx = dup2(w.x), wy = dup2(w.y), wz = dup2(w.z), ww = dup2(w.w);
            fma2(a0, wx, r0.x); fma2(a1, wx, r0.y);
            fma2(a0, wy, r1.x); fma2(a1, wy, r1.y);
            fma2(a0, wz, r2.x); fma2(a1, wz, r2.y);
            fma2(a0, ww, r3.x); fma2(a1, ww, r3.y);
        }
        float2 fA = unpk2(a0), fB = unpk2(a1);
        *(float4*)&s_sim[c * STR + k0] = make_float4(fA.x, fA.y, fB.x, fB.y);   // s2
    }
    __syncthreads();

    // ---- Phase G: per-channel softmax over k, aggregate with v_g ----
    if (t < DIM) {
        int c = t;
        float mx = -3.4e38f;
#pragma unroll
        for (int k = 0; k < KNB; k++) mx = fmaxf(mx, s_sim[c * STR + k]);
        float sum = 0.f, acc = 0.f;
#pragma unroll
        for (int k = 0; k < KNB; k++) {
            float e = expf(s_sim[c * STR + k] - mx);
            sum += e;
            acc += e * s_vg[c * STR + k];
        }
        out[(c * NPTS + n) * NA + a] = acc / sum;
    }
}

// ===================================================================
extern "C" void kernel_launch(void* const* d_in, const int* in_sizes, int n_in,
                              void* d_out, int out_size)
{
    const float* xyz       = (const float*)d_in[0];   // [1,3,1024]
    const float* feats     = (const float*)d_in[1];   // [1,64,1024,12]
    const float* anchors   = (const float*)d_in[2];   // [12,3,3]
    const float* to_qkv    = (const float*)d_in[3];   // [192,64]
    const float* pos_mlp1  = (const float*)d_in[4];   // [64,3]
    const float* pos_mlp2  = (const float*)d_in[5];   // [64,64]
    const float* attn_mlp1 = (const float*)d_in[6];   // [256,64]
    const float* attn_mlp2 = (const float*)d_in[7];   // [64,256]
    float* out = (float*)d_out;                       // [1,64,1024,12]

    prep_kernel<<<NPTS, 256>>>(xyz, feats, to_qkv);
    attn_kernel<<<NPTS * NA, 256>>>(xyz, anchors, pos_mlp1, pos_mlp2,
                                    attn_mlp1, attn_mlp2, out);
}

// round 5
// speedup vs baseline: 1.8985x; 1.8985x over previous
#include <cuda_runtime.h>
#include <math.h>

#define NPTS 1024
#define KNB  16
#define DIM  64
#define NA   12
#define PH   64
#define AH   256
#define STR  20   // shared row stride (floats): 16B-aligned + bank-spread

typedef unsigned long long u64t;

// ---- scratch (device globals; no allocation allowed) ----
__device__ int   g_idx[NPTS * KNB];
__device__ float g_q[NPTS * NA * DIM];
__device__ float g_k[NPTS * NA * DIM];
__device__ float g_v[NPTS * NA * DIM];
// transposed weights (coalesced per-warp loads: lanes span contiguous 128B)
__device__ float g_w1t[DIM * AH];   // [c][r]  = W1[r][c]
__device__ float g_w2t[AH * DIM];   // [h][c]  = W2[c][h]
__device__ float g_p2t[PH * DIM];   // [j][c]  = P2[c][j]

// ---- packed fp32x2 helpers (Blackwell FFMA2 pipe) ----
__device__ __forceinline__ u64t dup2(float v) {
    u64t r; asm("mov.b64 %0, {%1,%1};" : "=l"(r) : "f"(v)); return r;
}
__device__ __forceinline__ void fma2(u64t& acc, u64t a, u64t b) {
    asm("fma.rn.f32x2 %0, %1, %2, %0;" : "+l"(acc) : "l"(a), "l"(b));
}
__device__ __forceinline__ float2 unpk2(u64t v) {
    float2 f; asm("mov.b64 {%0,%1}, %2;" : "=f"(f.x), "=f"(f.y) : "l"(v)); return f;
}

// ===================================================================
// Kernel 0: transpose weights into coalescing-friendly layouts.
// ===================================================================
__global__ __launch_bounds__(256) void wprep_kernel(
    const float* __restrict__ W1,   // [256][64]
    const float* __restrict__ W2,   // [64][256]
    const float* __restrict__ P2)   // [64][64]
{
    int i = blockIdx.x * 256 + threadIdx.x;
    if (i < AH * DIM) {                       // W1T[c][r] = W1[r][c]
        int r = i >> 6, c = i & 63;
        g_w1t[c * AH + r] = W1[i];
    }
    if (i < DIM * AH) {                       // W2T[h][c] = W2[c][h]
        int c = i >> 8, h = i & 255;
        g_w2t[h * DIM + c] = W2[i];
    }
    if (i < DIM * PH) {                       // P2T[j][c] = P2[c][j]
        int c = i >> 6, j = i & 63;
        g_p2t[j * DIM + c] = P2[i];
    }
}

// ===================================================================
// Kernel 1: fused KNN + QKV. One 256-thread block per point n.
// QKV output TRANSPOSED to [n][a][c] so attn gathers are contiguous.
// ===================================================================
__global__ __launch_bounds__(256) void prep_kernel(
    const float* __restrict__ xyz,       // [3][1024]
    const float* __restrict__ feats,     // [64][1024][12]
    const float* __restrict__ to_qkv)    // [192][64]
{
    __shared__ float sf[DIM * NA];
    int n = blockIdx.x;
    int t = threadIdx.x;

    if (t < 32) {
        int lane = t;
        float px = xyz[n], py = xyz[NPTS + n], pz = xyz[2 * NPTS + n];
        float sqn = px * px + py * py + pz * pz;
        float d[32];
#pragma unroll
        for (int j = 0; j < 32; j++) {
            int m = lane + j * 32;
            float qx = xyz[m], qy = xyz[NPTS + m], qz = xyz[2 * NPTS + m];
            float sqm = qx * qx + qy * qy + qz * qz;
            d[j] = sqn + sqm - 2.0f * (px * qx + py * qy + pz * qz);
        }
        for (int tt = 0; tt < KNB; tt++) {
            float best = 3.4e38f;
            int bidx = 1 << 30;
#pragma unroll
            for (int j = 0; j < 32; j++) {
                int m = lane + j * 32;
                if (d[j] < best || (d[j] == best && m < bidx)) { best = d[j]; bidx = m; }
            }
#pragma unroll
            for (int off = 16; off; off >>= 1) {
                float ob = __shfl_xor_sync(0xffffffffu, best, off);
                int   oi = __shfl_xor_sync(0xffffffffu, bidx, off);
                if (ob < best || (ob == best && oi < bidx)) { best = ob; bidx = oi; }
            }
            if (lane == 0) g_idx[n * KNB + tt] = bidx;
            if ((bidx & 31) == lane) {
                int jj = bidx >> 5;
#pragma unroll
                for (int j = 0; j < 32; j++) if (j == jj) d[j] = 3.4e38f;
            }
        }
    } else {
        for (int idx = t - 32; idx < DIM * NA; idx += 224) {
            int i = idx / NA, a = idx % NA;
            sf[idx] = feats[(i * NPTS + n) * NA + a];
        }
    }
    __syncthreads();

    for (int o = t; o < 3 * DIM * NA; o += 256) {
        int j = o / NA, a = o % NA;
        const float* w = to_qkv + j * DIM;
        float acc = 0.0f;
#pragma unroll 16
        for (int i = 0; i < DIM; i++) acc += w[i] * sf[i * NA + a];
        int c = j & (DIM - 1);
        float* dst = (j < DIM) ? g_q : (j < 2 * DIM ? g_k : g_v);
        dst[(n * NA + a) * DIM + c] = acc;
    }
}

// ===================================================================
// Kernel 2: fused attention. One 256-thread block per (n, a).
// All GEMM phases use 4x4 register tiles + transposed weights:
// per inner step: 1 coalesced LDG.128 (1 line/warp) + 1 LDS.128
// (64B, conflict-free) + 8 FFMA2.
// ===================================================================
__global__ __launch_bounds__(256) void attn_kernel(
    const float* __restrict__ xyz,       // [3][1024]
    const float* __restrict__ anchors,   // [12][3][3]
    const float* __restrict__ P1,        // [64][3]
    float* __restrict__ out)             // [64][1024][12]
{
    __shared__ float s_q[DIM];
    __shared__ float s_gx[3][KNB];
    __shared__ int   s_idx[KNB];
    __shared__ float s_sim[DIM * STR];   // sim; reused for s2 after F
    __shared__ float s_vg[DIM * STR];
    __shared__ float s_h[AH * STR];      // h; pe1 aliases the front
    __shared__ float s_part[4 * DIM * KNB];  // 4-way reduction partials
    float* s_pe1 = s_h;

    int a = blockIdx.x % NA;
    int n = blockIdx.x / NA;
    int t = threadIdx.x;

    // ---- Phase A: neighbor idx, rotated rel pos, q load ----
    if (t < KNB) {
        int m = g_idx[n * KNB + t];
        s_idx[t] = m;
        float rx = xyz[n]            - xyz[m];
        float ry = xyz[NPTS + n]     - xyz[NPTS + m];
        float rz = xyz[2 * NPTS + n] - xyz[2 * NPTS + m];
        const float* A = anchors + a * 9;
        s_gx[0][t] = A[0] * rx + A[1] * ry + A[2] * rz;
        s_gx[1][t] = A[3] * rx + A[4] * ry + A[5] * rz;
        s_gx[2][t] = A[6] * rx + A[7] * ry + A[8] * rz;
    }
    if (t >= 64 && t < 64 + DIM) {
        int c = t - 64;
        s_q[c] = g_q[(n * NA + a) * DIM + c];
    }
    __syncthreads();

    // ---- Phase B: pe1[j][k] = relu(P1[j,:] . gx[:,k]) ----
    {
        int j = t >> 2, k0 = (t & 3) * 4;
        float p0 = P1[j * 3 + 0], p1 = P1[j * 3 + 1], p2 = P1[j * 3 + 2];
        float4 r;
        r.x = fmaxf(p0 * s_gx[0][k0 + 0] + p1 * s_gx[1][k0 + 0] + p2 * s_gx[2][k0 + 0], 0.0f);
        r.y = fmaxf(p0 * s_gx[0][k0 + 1] + p1 * s_gx[1][k0 + 1] + p2 * s_gx[2][k0 + 1], 0.0f);
        r.z = fmaxf(p0 * s_gx[0][k0 + 2] + p1 * s_gx[1][k0 + 2] + p2 * s_gx[2][k0 + 2], 0.0f);
        r.w = fmaxf(p0 * s_gx[0][k0 + 3] + p1 * s_gx[1][k0 + 3] + p2 * s_gx[2][k0 + 3], 0.0f);
        *(float4*)&s_pe1[j * STR + k0] = r;
    }
    __syncthreads();

    // ---- Phase C: pe = P2 @ pe1 (4c x 4k tiles, 4-way j-split) ----
    {
        int q = t >> 6, rem = t & 63, cg = rem >> 2, kg = rem & 3;
        u64t a00 = 0, a01 = 0, a10 = 0, a11 = 0, a20 = 0, a21 = 0, a30 = 0, a31 = 0;
#pragma unroll 4
        for (int j = 16 * q; j < 16 * q + 16; j++) {
            float4 w = __ldg((const float4*)(g_p2t + j * DIM + 4 * cg));
            ulonglong2 pv = *(const ulonglong2*)&s_pe1[j * STR + 4 * kg];
            u64t w0 = dup2(w.x), w1 = dup2(w.y), w2 = dup2(w.z), w3 = dup2(w.w);
            fma2(a00, w0, pv.x); fma2(a01, w0, pv.y);
            fma2(a10, w1, pv.x); fma2(a11, w1, pv.y);
            fma2(a20, w2, pv.x); fma2(a21, w2, pv.y);
            fma2(a30, w3, pv.x); fma2(a31, w3, pv.y);
        }
        float* pb = s_part + ((q * DIM + 4 * cg) * KNB + 4 * kg);
        float2 f;
        f = unpk2(a00); ((float2*)(pb + 0 * KNB))[0] = f; f = unpk2(a01); ((float2*)(pb + 0 * KNB))[1] = f;
        f = unpk2(a10); ((float2*)(pb + 1 * KNB))[0] = f; f = unpk2(a11); ((float2*)(pb + 1 * KNB))[1] = f;
        f = unpk2(a20); ((float2*)(pb + 2 * KNB))[0] = f; f = unpk2(a21); ((float2*)(pb + 2 * KNB))[1] = f;
        f = unpk2(a30); ((float2*)(pb + 3 * KNB))[0] = f; f = unpk2(a31); ((float2*)(pb + 3 * KNB))[1] = f;
    }
    __syncthreads();

    // ---- Phase C2: reduce pe partials; gather k/v; build sim, v_g ----
    {
        int c = t >> 2, k0 = (t & 3) * 4;
        float4 p0 = *(const float4*)&s_part[(0 * DIM + c) * KNB + k0];
        float4 p1 = *(const float4*)&s_part[(1 * DIM + c) * KNB + k0];
        float4 p2 = *(const float4*)&s_part[(2 * DIM + c) * KNB + k0];
        float4 p3 = *(const float4*)&s_part[(3 * DIM + c) * KNB + k0];
        float4 pe = make_float4(p0.x + p1.x + p2.x + p3.x,
                                p0.y + p1.y + p2.y + p3.y,
                                p0.z + p1.z + p2.z + p3.z,
                                p0.w + p1.w + p2.w + p3.w);
        float qc = s_q[c];
        int m0 = s_idx[k0 + 0], m1 = s_idx[k0 + 1], m2 = s_idx[k0 + 2], m3 = s_idx[k0 + 3];
        int b0 = (m0 * NA + a) * DIM + c;
        int b1 = (m1 * NA + a) * DIM + c;
        int b2 = (m2 * NA + a) * DIM + c;
        int b3 = (m3 * NA + a) * DIM + c;
        float4 sim, vg;
        sim.x = qc - g_k[b0] + pe.x;  vg.x = g_v[b0] + pe.x;
        sim.y = qc - g_k[b1] + pe.y;  vg.y = g_v[b1] + pe.y;
        sim.z = qc - g_k[b2] + pe.z;  vg.z = g_v[b2] + pe.z;
        sim.w = qc - g_k[b3] + pe.w;  vg.w = g_v[b3] + pe.w;
        *(float4*)&s_sim[c * STR + k0] = sim;
        *(float4*)&s_vg[c * STR + k0]  = vg;
    }
    __syncthreads();

    // ---- Phase E: h = relu(W1 @ sim), 4r x 4k tiles ----
    {
        int rg = t >> 2, kg = t & 3;
        u64t a00 = 0, a01 = 0, a10 = 0, a11 = 0, a20 = 0, a21 = 0, a30 = 0, a31 = 0;
#pragma unroll 4
        for (int c = 0; c < DIM; c++) {
            float4 w = __ldg((const float4*)(g_w1t + c * AH + 4 * rg));
            ulonglong2 sv = *(const ulonglong2*)&s_sim[c * STR + 4 * kg];
            u64t w0 = dup2(w.x), w1 = dup2(w.y), w2 = dup2(w.z), w3 = dup2(w.w);
            fma2(a00, w0, sv.x); fma2(a01, w0, sv.y);
            fma2(a10, w1, sv.x); fma2(a11, w1, sv.y);
            fma2(a20, w2, sv.x); fma2(a21, w2, sv.y);
            fma2(a30, w3, sv.x); fma2(a31, w3, sv.y);
        }
        float2 f0, f1;
        float* hb = s_h + (4 * rg) * STR + 4 * kg;
        f0 = unpk2(a00); f1 = unpk2(a01);
        *(float4*)(hb + 0 * STR) = make_float4(fmaxf(f0.x,0.f), fmaxf(f0.y,0.f), fmaxf(f1.x,0.f), fmaxf(f1.y,0.f));
        f0 = unpk2(a10); f1 = unpk2(a11);
        *(float4*)(hb + 1 * STR) = make_float4(fmaxf(f0.x,0.f), fmaxf(f0.y,0.f), fmaxf(f1.x,0.f), fmaxf(f1.y,0.f));
        f0 = unpk2(a20); f1 = unpk2(a21);
        *(float4*)(hb + 2 * STR) = make_float4(fmaxf(f0.x,0.f), fmaxf(f0.y,0.f), fmaxf(f1.x,0.f), fmaxf(f1.y,0.f));
        f0 = unpk2(a30); f1 = unpk2(a31);
        *(float4*)(hb + 3 * STR) = make_float4(fmaxf(f0.x,0.f), fmaxf(f0.y,0.f), fmaxf(f1.x,0.f), fmaxf(f1.y,0.f));
    }
    __syncthreads();

    // ---- Phase F: s2 = W2 @ h (4c x 4k tiles, 4-way h-split) ----
    {
        int q = t >> 6, rem = t & 63, cg = rem >> 2, kg = rem & 3;
        u64t a00 = 0, a01 = 0, a10 = 0, a11 = 0, a20 = 0, a21 = 0, a30 = 0, a31 = 0;
#pragma unroll 4
        for (int hh = 64 * q; hh < 64 * q + 64; hh++) {
            float4 w = __ldg((const float4*)(g_w2t + hh * DIM + 4 * cg));
            ulonglong2 hv = *(const ulonglong2*)&s_h[hh * STR + 4 * kg];
            u64t w0 = dup2(w.x), w1 = dup2(w.y), w2 = dup2(w.z), w3 = dup2(w.w);
            fma2(a00, w0, hv.x); fma2(a01, w0, hv.y);
            fma2(a10, w1, hv.x); fma2(a11, w1, hv.y);
            fma2(a20, w2, hv.x); fma2(a21, w2, hv.y);
            fma2(a30, w3, hv.x); fma2(a31, w3, hv.y);
        }
        float* pb = s_part + ((q * DIM + 4 * cg) * KNB + 4 * kg);
        float2 f;
        f = unpk2(a00); ((float2*)(pb + 0 * KNB))[0] = f; f = unpk2(a01); ((float2*)(pb + 0 * KNB))[1] = f;
        f = unpk2(a10); ((float2*)(pb + 1 * KNB))[0] = f; f = unpk2(a11); ((float2*)(pb + 1 * KNB))[1] = f;
        f = unpk2(a20); ((float2*)(pb + 2 * KNB))[0] = f; f = unpk2(a21); ((float2*)(pb + 2 * KNB))[1] = f;
        f = unpk2(a30); ((float2*)(pb + 3 * KNB))[0] = f; f = unpk2(a31); ((float2*)(pb + 3 * KNB))[1] = f;
    }
    __syncthreads();

    // ---- Phase F2: reduce s2 partials into s_sim ----
    {
        int c = t >> 2, k0 = (t & 3) * 4;
        float4 p0 = *(const float4*)&s_part[(0 * DIM + c) * KNB + k0];
        float4 p1 = *(const float4*)&s_part[(1 * DIM + c) * KNB + k0];
        float4 p2 = *(const float4*)&s_part[(2 * DIM + c) * KNB + k0];
        float4 p3 = *(const float4*)&s_part[(3 * DIM + c) * KNB + k0];
        *(float4*)&s_sim[c * STR + k0] = make_float4(
            p0.x + p1.x + p2.x + p3.x, p0.y + p1.y + p2.y + p3.y,
            p0.z + p1.z + p2.z + p3.z, p0.w + p1.w + p2.w + p3.w);
    }
    __syncthreads();

    // ---- Phase G: per-channel softmax over k, aggregate with v_g ----
    if (t < DIM) {
        int c = t;
        float mx = -3.4e38f;
#pragma unroll
        for (int k = 0; k < KNB; k++) mx = fmaxf(mx, s_sim[c * STR + k]);
        float sum = 0.f, acc = 0.f;
#pragma unroll
        for (int k = 0; k < KNB; k++) {
            float e = expf(s_sim[c * STR + k] - mx);
            sum += e;
            acc += e * s_vg[c * STR + k];
        }
        out[(c * NPTS + n) * NA + a] = acc / sum;
    }
}

// ===================================================================
extern "C" void kernel_launch(void* const* d_in, const int* in_sizes, int n_in,
                              void* d_out, int out_size)
{
    const float* xyz       = (const float*)d_in[0];   // [1,3,1024]
    const float* feats     = (const float*)d_in[1];   // [1,64,1024,12]
    const float* anchors   = (const float*)d_in[2];   // [12,3,3]
    const float* to_qkv    = (const float*)d_in[3];   // [192,64]
    const float* pos_mlp1  = (const float*)d_in[4];   // [64,3]
    const float* pos_mlp2  = (const float*)d_in[5];   // [64,64]
    const float* attn_mlp1 = (const float*)d_in[6];   // [256,64]
    const float* attn_mlp2 = (const float*)d_in[7];   // [64,256]
    float* out = (float*)d_out;                       // [1,64,1024,12]

    wprep_kernel<<<64, 256>>>(attn_mlp1, attn_mlp2, pos_mlp2);
    prep_kernel<<<NPTS, 256>>>(xyz, feats, to_qkv);
    attn_kernel<<<NPTS * NA, 256>>>(xyz, anchors, pos_mlp1, out);
}